// round 3
// baseline (speedup 1.0000x reference)
#include <cuda_runtime.h>
#include <mma.h>
#include <cstdint>
#include <cstddef>

using namespace nvcuda;

// Problem constants
#define BATCH 2
#define SEQ   2048
#define DIM   1024
#define NH    16
#define HD    64
#define ATT_SCALE 0.125f   // 1/sqrt(64)

// Scratch (allocation-free rule: __device__ globals)
__device__ float g_Q[BATCH * SEQ * DIM];
__device__ float g_K[BATCH * SEQ * DIM];
__device__ float g_V[BATCH * SEQ * DIM];
__device__ float g_Ctx[BATCH * SEQ * DIM];

// round-to-tf32 helper (values stored in smem are exactly tf32-representable,
// so the hardware mma's operand handling is a no-op and we skip all
// fragment-level conversions)
__device__ __forceinline__ float to_tf32(float x) {
    return wmma::__float_to_tf32(x);
}

// fast exp via FMA pipe (keeps MUFU free): exp(x) = 2^n * e^r,
// n = rint(x*log2e), r = x - n*ln2, e^r deg-5 Taylor (|r|<=0.347, err ~2.4e-6)
__device__ __forceinline__ float fast_exp(float x) {
    float n = rintf(x * 1.4426950408889634f);
    float r = fmaf(n, -0.6931471805599453f, x);
    float e = fmaf(r, 8.3333337e-3f, 4.1666668e-2f);   // 1/120, 1/24
    e = fmaf(r, e, 0.16666667f);
    e = fmaf(r, e, 0.5f);
    e = fmaf(r, e, 1.0f);
    e = fmaf(r, e, 1.0f);
    int ni = (int)n;
    float scale = __int_as_float((ni + 127) << 23);
    return e * scale;
}

// ---------------------------------------------------------------------------
// TF32 GEMM + bias: C[M,N] = A[M,K] @ W[K,N] + bias[N]
// 128x128x32 block tile, 8 warps (2x4), each warp 64x32 via wmma 16x16x8.
// Operands pre-rounded to tf32 on smem store; bias folded into acc init.
// qkv_sel >= 0 fuses the 3 projections into one launch (blockIdx.z selects).
// ---------------------------------------------------------------------------
#define GBM 128
#define GBN 128
#define GBK 32
#define A_LD 36     // 32 + 4 pad
#define B_LD 132    // 128 + 4 pad

__global__ __launch_bounds__(256)
void gemm_tf32_bias(const float* __restrict__ A0, const float* __restrict__ W0,
                    const float* __restrict__ bias0, float* __restrict__ C0,
                    const float* __restrict__ A1, const float* __restrict__ W1,
                    const float* __restrict__ bias1, float* __restrict__ C1,
                    const float* __restrict__ A2, const float* __restrict__ W2,
                    const float* __restrict__ bias2, float* __restrict__ C2,
                    int M, int N, int K)
{
    __shared__ float As[GBM][A_LD];   // 128x36 = 18432B
    __shared__ float Bs[GBK][B_LD];   // 32x132 = 16896B

    const int z = blockIdx.z;
    const float* A    = (z == 0) ? A0    : (z == 1) ? A1    : A2;
    const float* W    = (z == 0) ? W0    : (z == 1) ? W1    : W2;
    const float* bias = (z == 0) ? bias0 : (z == 1) ? bias1 : bias2;
    float*       C    = (z == 0) ? C0    : (z == 1) ? C1    : C2;

    const int tid = threadIdx.x;
    const int w   = tid >> 5;
    const int wm  = w >> 2;    // 0..1 -> 64 rows each
    const int wn  = w & 3;     // 0..3 -> 32 cols each
    const int row0 = blockIdx.y * GBM;
    const int col0 = blockIdx.x * GBN;

    // bias tile (replicated 16 rows) aliased into As (used only before main loop)
    float* BiasS = &As[0][0];  // ld = B_LD, 16*132 floats <= 128*36
    for (int idx = tid; idx < 16 * 128; idx += 256) {
        int r = idx >> 7, c = idx & 127;
        BiasS[r * B_LD + c] = bias[col0 + c];
    }
    __syncthreads();

    wmma::fragment<wmma::accumulator, 16, 16, 8, float> acc[4][2];
#pragma unroll
    for (int mf = 0; mf < 4; mf++)
#pragma unroll
        for (int nf = 0; nf < 2; nf++)
            wmma::load_matrix_sync(acc[mf][nf], &BiasS[wn * 32 + nf * 16],
                                   B_LD, wmma::mem_row_major);
    __syncthreads();

    for (int kt = 0; kt < K; kt += GBK) {
        // ---- load A tile 128x32 (1024 quads, 4/thread), pre-round to tf32 ----
#pragma unroll
        for (int it = 0; it < 4; it++) {
            int q   = tid + it * 256;
            int row = q >> 3;          // 0..127
            int kq  = q & 7;           // quad within row
            float4 v = *reinterpret_cast<const float4*>(
                A + (size_t)(row0 + row) * K + kt + kq * 4);
            As[row][kq * 4 + 0] = to_tf32(v.x);
            As[row][kq * 4 + 1] = to_tf32(v.y);
            As[row][kq * 4 + 2] = to_tf32(v.z);
            As[row][kq * 4 + 3] = to_tf32(v.w);
        }
        // ---- load B tile 32x128 (1024 quads, 4/thread), pre-round ----
#pragma unroll
        for (int it = 0; it < 4; it++) {
            int q  = tid + it * 256;
            int kk = q >> 5;           // 0..31
            int n4 = q & 31;
            float4 v = *reinterpret_cast<const float4*>(
                W + (size_t)(kt + kk) * N + col0 + n4 * 4);
            Bs[kk][n4 * 4 + 0] = to_tf32(v.x);
            Bs[kk][n4 * 4 + 1] = to_tf32(v.y);
            Bs[kk][n4 * 4 + 2] = to_tf32(v.z);
            Bs[kk][n4 * 4 + 3] = to_tf32(v.w);
        }
        __syncthreads();

#pragma unroll
        for (int ks = 0; ks < 4; ks++) {
            const int k0 = ks * 8;
            wmma::fragment<wmma::matrix_a, 16, 16, 8, wmma::precision::tf32, wmma::row_major> af[4];
            wmma::fragment<wmma::matrix_b, 16, 16, 8, wmma::precision::tf32, wmma::row_major> bf[2];
#pragma unroll
            for (int mf = 0; mf < 4; mf++)
                wmma::load_matrix_sync(af[mf], &As[wm * 64 + mf * 16][k0], A_LD);
#pragma unroll
            for (int nf = 0; nf < 2; nf++)
                wmma::load_matrix_sync(bf[nf], &Bs[k0][wn * 32 + nf * 16], B_LD);
#pragma unroll
            for (int mf = 0; mf < 4; mf++)
#pragma unroll
                for (int nf = 0; nf < 2; nf++)
                    wmma::mma_sync(acc[mf][nf], af[mf], bf[nf], acc[mf][nf]);
        }
        __syncthreads();
    }

#pragma unroll
    for (int mf = 0; mf < 4; mf++)
#pragma unroll
        for (int nf = 0; nf < 2; nf++)
            wmma::store_matrix_sync(
                C + (size_t)(row0 + wm * 64 + mf * 16) * N + col0 + wn * 32 + nf * 16,
                acc[mf][nf], N, wmma::mem_row_major);
}

// ---------------------------------------------------------------------------
// Masked attention, tf32 tensor cores, no max subtraction (scores bounded).
// Q/K/V pre-rounded to tf32 at smem store; exp on FMA pipe; P pre-rounded.
// Grid: (S/64, H, B). Block: 256 threads = 8 warps (2m x 4n over 64x64 tile).
// ---------------------------------------------------------------------------
#define TS  64
#define PAD 68

__global__ __launch_bounds__(256)
void attn_tf32(const int* __restrict__ mask, float* __restrict__ Og)
{
    extern __shared__ float sm[];
    float* Qs = sm;                 // [64][68]
    float* Ks = sm + TS * PAD;      // [64][68]
    float* Vs = sm + 2 * TS * PAD;  // [64][68]
    float* Ps = sm + 3 * TS * PAD;  // [64][68]

    const int qt = blockIdx.x;
    const int h  = blockIdx.y;
    const int b  = blockIdx.z;
    const int s0 = qt * TS;
    const int tid = threadIdx.x;
    const int w   = tid >> 5;
    const int wm  = w >> 2;   // 0..1 : 32 rows each
    const int wn  = w & 3;    // 0..3 : 16 cols each
    const int tx  = tid & 15;
    const int ty  = tid >> 4;
    const int r0  = ty * 4;

    const float* Qbase = g_Q + ((size_t)b * SEQ + s0) * DIM + h * HD;
    const float* Kbase = g_K + (size_t)b * SEQ * DIM + h * HD;
    const float* Vbase = g_V + (size_t)b * SEQ * DIM + h * HD;

    // load Q tile: 64x64, 1024 quads, pre-rounded
#pragma unroll
    for (int it = 0; it < 4; it++) {
        int lin = tid + it * 256;
        int row = lin >> 4, q4 = lin & 15;
        float4 v = *reinterpret_cast<const float4*>(Qbase + (size_t)row * DIM + q4 * 4);
        Qs[row * PAD + q4 * 4 + 0] = to_tf32(v.x);
        Qs[row * PAD + q4 * 4 + 1] = to_tf32(v.y);
        Qs[row * PAD + q4 * 4 + 2] = to_tf32(v.z);
        Qs[row * PAD + q4 * 4 + 3] = to_tf32(v.w);
    }

    wmma::fragment<wmma::accumulator, 16, 16, 8, float> ofrag[2];
#pragma unroll
    for (int f = 0; f < 2; f++) wmma::fill_fragment(ofrag[f], 0.f);

    float l_i[4] = {0.f, 0.f, 0.f, 0.f};

    for (int kt = 0; kt < SEQ; kt += TS) {
        // ---- load K and V tiles, pre-rounded ----
#pragma unroll
        for (int it = 0; it < 4; it++) {
            int lin = tid + it * 256;
            int row = lin >> 4, q4 = lin & 15;
            float4 kv = *reinterpret_cast<const float4*>(Kbase + (size_t)(kt + row) * DIM + q4 * 4);
            float4 vv = *reinterpret_cast<const float4*>(Vbase + (size_t)(kt + row) * DIM + q4 * 4);
            Ks[row * PAD + q4 * 4 + 0] = to_tf32(kv.x);
            Ks[row * PAD + q4 * 4 + 1] = to_tf32(kv.y);
            Ks[row * PAD + q4 * 4 + 2] = to_tf32(kv.z);
            Ks[row * PAD + q4 * 4 + 3] = to_tf32(kv.w);
            Vs[row * PAD + q4 * 4 + 0] = to_tf32(vv.x);
            Vs[row * PAD + q4 * 4 + 1] = to_tf32(vv.y);
            Vs[row * PAD + q4 * 4 + 2] = to_tf32(vv.z);
            Vs[row * PAD + q4 * 4 + 3] = to_tf32(vv.w);
        }
        __syncthreads();

        // ---- S = Q @ K^T via tf32 wmma (no conversions; operands pre-rounded) ----
        wmma::fragment<wmma::accumulator, 16, 16, 8, float> sfrag[2];
#pragma unroll
        for (int f = 0; f < 2; f++) wmma::fill_fragment(sfrag[f], 0.f);

#pragma unroll
        for (int d0 = 0; d0 < HD; d0 += 8) {
            wmma::fragment<wmma::matrix_a, 16, 16, 8, wmma::precision::tf32, wmma::row_major> aq[2];
            wmma::fragment<wmma::matrix_b, 16, 16, 8, wmma::precision::tf32, wmma::col_major> bk;
#pragma unroll
            for (int f = 0; f < 2; f++)
                wmma::load_matrix_sync(aq[f], &Qs[(wm * 32 + f * 16) * PAD + d0], PAD);
            wmma::load_matrix_sync(bk, &Ks[(wn * 16) * PAD + d0], PAD);
#pragma unroll
            for (int f = 0; f < 2; f++)
                wmma::mma_sync(sfrag[f], aq[f], bk, sfrag[f]);
        }
#pragma unroll
        for (int f = 0; f < 2; f++)
            wmma::store_matrix_sync(&Ps[(wm * 32 + f * 16) * PAD + wn * 16],
                                    sfrag[f], PAD, wmma::mem_row_major);
        __syncthreads();

        // ---- p = keep ? exp(s/8) : 0 (FMA-pipe exp), row sums, pre-round P ----
#pragma unroll
        for (int i = 0; i < 4; i++) {
            const int row = r0 + i;
            const int* mrow = mask + (size_t)(s0 + row) * SEQ + kt;
            float rs = 0.f;
#pragma unroll
            for (int j = 0; j < 4; j++) {
                int c = tx + 16 * j;
                float v = Ps[row * PAD + c];
                float p = mrow[c] ? fast_exp(v * ATT_SCALE) : 0.f;
                rs += p;
                Ps[row * PAD + c] = to_tf32(p);
            }
            rs += __shfl_xor_sync(0xffffffffu, rs, 1);
            rs += __shfl_xor_sync(0xffffffffu, rs, 2);
            rs += __shfl_xor_sync(0xffffffffu, rs, 4);
            rs += __shfl_xor_sync(0xffffffffu, rs, 8);
            l_i[i] += rs;
        }
        __syncthreads();

        // ---- O += P @ V via tf32 wmma ----
#pragma unroll
        for (int t0 = 0; t0 < TS; t0 += 8) {
            wmma::fragment<wmma::matrix_a, 16, 16, 8, wmma::precision::tf32, wmma::row_major> ap[2];
            wmma::fragment<wmma::matrix_b, 16, 16, 8, wmma::precision::tf32, wmma::row_major> bv;
#pragma unroll
            for (int f = 0; f < 2; f++)
                wmma::load_matrix_sync(ap[f], &Ps[(wm * 32 + f * 16) * PAD + t0], PAD);
            wmma::load_matrix_sync(bv, &Vs[t0 * PAD + wn * 16], PAD);
#pragma unroll
            for (int f = 0; f < 2; f++)
                wmma::mma_sync(ofrag[f], ap[f], bv, ofrag[f]);
        }
        __syncthreads();
    }

    // ---- finalize: O to smem, divide by row sums, write context ----
#pragma unroll
    for (int f = 0; f < 2; f++)
        wmma::store_matrix_sync(&Ps[(wm * 32 + f * 16) * PAD + wn * 16],
                                ofrag[f], PAD, wmma::mem_row_major);
    __syncthreads();

#pragma unroll
    for (int i = 0; i < 4; i++) {
        float inv = 1.f / l_i[i];
        float* orow = Og + ((size_t)b * SEQ + s0 + r0 + i) * DIM + h * HD;
#pragma unroll
        for (int ww = 0; ww < 4; ww++) {
            int c = tx + 16 * ww;
            orow[c] = Ps[(r0 + i) * PAD + c] * inv;
        }
    }
}

// ---------------------------------------------------------------------------
// Launch
// ---------------------------------------------------------------------------
extern "C" void kernel_launch(void* const* d_in, const int* in_sizes, int n_in,
                              void* d_out, int out_size)
{
    const float* query = (const float*)d_in[0];
    const float* key   = (const float*)d_in[1];
    const float* value = (const float*)d_in[2];
    const int*   mask  = (const int*)  d_in[3];
    const float* Wq = (const float*)d_in[4];
    const float* bq = (const float*)d_in[5];
    const float* Wk = (const float*)d_in[6];
    const float* bk = (const float*)d_in[7];
    const float* Wv = (const float*)d_in[8];
    const float* bv = (const float*)d_in[9];
    const float* Wo = (const float*)d_in[10];
    const float* bo = (const float*)d_in[11];
    float* out = (float*)d_out;

    float *pQ, *pK, *pV, *pC;
    cudaGetSymbolAddress((void**)&pQ, g_Q);
    cudaGetSymbolAddress((void**)&pK, g_K);
    cudaGetSymbolAddress((void**)&pV, g_V);
    cudaGetSymbolAddress((void**)&pC, g_Ctx);

    const int M = BATCH * SEQ;   // 4096
    const int N = DIM;           // 1024
    const int K = DIM;           // 1024

    // Fused Q/K/V projections: grid.z selects the problem
    dim3 qkv_grid(N / GBN, M / GBM, 3);  // (8, 32, 3)
    gemm_tf32_bias<<<qkv_grid, 256>>>(query, Wq, bq, pQ,
                                      key,   Wk, bk, pK,
                                      value, Wv, bv, pV, M, N, K);

    // Attention
    const int attn_smem = 4 * TS * PAD * (int)sizeof(float);  // 69632 B
    cudaFuncSetAttribute(attn_tf32, cudaFuncAttributeMaxDynamicSharedMemorySize, attn_smem);
    attn_tf32<<<dim3(SEQ / TS, NH, BATCH), 256, attn_smem>>>(mask, pC);

    // Output projection
    dim3 ggrid(N / GBN, M / GBM, 1);
    gemm_tf32_bias<<<ggrid, 256>>>(pC, Wo, bo, out,
                                   pC, Wo, bo, out,
                                   pC, Wo, bo, out, M, N, K);
}

// round 4
// speedup vs baseline: 1.1479x; 1.1479x over previous
#include <cuda_runtime.h>
#include <mma.h>
#include <cstdint>
#include <cstddef>

using namespace nvcuda;

// Problem constants
#define BATCH 2
#define SEQ   2048
#define DIM   1024
#define NH    16
#define HD    64
#define ATT_SCALE 0.125f   // 1/sqrt(64)
#define MBW   (SEQ / 32)   // 64 mask words per row

// Scratch (allocation-free rule: __device__ globals)
__device__ float g_Q[BATCH * SEQ * DIM];
__device__ float g_K[BATCH * SEQ * DIM];
__device__ float g_V[BATCH * SEQ * DIM];
__device__ float g_Ctx[BATCH * SEQ * DIM];
__device__ uint32_t g_MB[SEQ * MBW];   // bitmask: bit (c&31) of word [r][c>>5]

__device__ __forceinline__ float to_tf32(float x) {
    return wmma::__float_to_tf32(x);
}

// fast exp on the FMA pipe (MUFU stays free)
__device__ __forceinline__ float fast_exp(float x) {
    float n = rintf(x * 1.4426950408889634f);
    float r = fmaf(n, -0.6931471805599453f, x);
    float e = fmaf(r, 8.3333337e-3f, 4.1666668e-2f);
    e = fmaf(r, e, 0.16666667f);
    e = fmaf(r, e, 0.5f);
    e = fmaf(r, e, 1.0f);
    e = fmaf(r, e, 1.0f);
    int ni = (int)n;
    return e * __int_as_float((ni + 127) << 23);
}

// ---------------------------------------------------------------------------
// mask (int32) -> bitmask words
// ---------------------------------------------------------------------------
__global__ __launch_bounds__(256)
void mask_bits_kernel(const int* __restrict__ mask)
{
    int idx = blockIdx.x * 256 + threadIdx.x;        // element index in [0, S*S)
    uint32_t bit = (mask[idx] != 0) ? 1u : 0u;
    uint32_t word = __ballot_sync(0xffffffffu, bit);
    if ((threadIdx.x & 31) == 0) g_MB[idx >> 5] = word;
}

// ---------------------------------------------------------------------------
// TF32 GEMM + bias, double-buffered smem (1 sync / k-step), 2 CTAs/SM.
// 128x128x16 tile, 8 warps (2x4), warp = 64x32 via wmma 16x16x8.
// blockIdx.z selects among up to 3 fused problems.
// ---------------------------------------------------------------------------
#define GBM 128
#define GBN 128
#define GBK 16
#define A_LD 20     // 16 + 4 pad
#define B_LD 132    // 128 + 4 pad

__global__ __launch_bounds__(256, 2)
void gemm_tf32_bias(const float* __restrict__ A0, const float* __restrict__ W0,
                    const float* __restrict__ bias0, float* __restrict__ C0,
                    const float* __restrict__ A1, const float* __restrict__ W1,
                    const float* __restrict__ bias1, float* __restrict__ C1,
                    const float* __restrict__ A2, const float* __restrict__ W2,
                    const float* __restrict__ bias2, float* __restrict__ C2,
                    int M, int N, int K)
{
    __shared__ float As[2][GBM * A_LD];   // 2*2560*4  = 20480B
    __shared__ float Bs[2][GBK * B_LD];   // 2*2112*4  = 16896B

    const int z = blockIdx.z;
    const float* A    = (z == 0) ? A0    : (z == 1) ? A1    : A2;
    const float* W    = (z == 0) ? W0    : (z == 1) ? W1    : W2;
    const float* bias = (z == 0) ? bias0 : (z == 1) ? bias1 : bias2;
    float*       C    = (z == 0) ? C0    : (z == 1) ? C1    : C2;

    const int tid = threadIdx.x;
    const int w   = tid >> 5;
    const int wm  = w >> 2;
    const int wn  = w & 3;
    const int row0 = blockIdx.y * GBM;
    const int col0 = blockIdx.x * GBN;

    // per-thread load coords (fixed across k-steps)
    const int aq0 = tid, aq1 = tid + 256;            // A quads
    const int ar0 = aq0 >> 2, ak0 = aq0 & 3;
    const int ar1 = aq1 >> 2, ak1 = aq1 & 3;
    const int br0 = aq0 >> 5, bn0 = aq0 & 31;        // B quads
    const int br1 = aq1 >> 5, bn1 = aq1 & 31;

    // bias tile aliased into Bs[1] (consumed into acc before iter0 overwrites)
    float* BiasS = &Bs[1][0];
    for (int idx = tid; idx < 16 * 128; idx += 256) {
        int r = idx >> 7, c = idx & 127;
        BiasS[r * B_LD + c] = bias[col0 + c];
    }
    __syncthreads();

    wmma::fragment<wmma::accumulator, 16, 16, 8, float> acc[4][2];
#pragma unroll
    for (int mf = 0; mf < 4; mf++)
#pragma unroll
        for (int nf = 0; nf < 2; nf++)
            wmma::load_matrix_sync(acc[mf][nf], &BiasS[wn * 32 + nf * 16],
                                   B_LD, wmma::mem_row_major);

    // prolog: stage k=0 into buffer 0
    {
        float4 a0 = *reinterpret_cast<const float4*>(A + (size_t)(row0 + ar0) * K + ak0 * 4);
        float4 a1 = *reinterpret_cast<const float4*>(A + (size_t)(row0 + ar1) * K + ak1 * 4);
        float4 b0 = *reinterpret_cast<const float4*>(W + (size_t)br0 * N + col0 + bn0 * 4);
        float4 b1 = *reinterpret_cast<const float4*>(W + (size_t)br1 * N + col0 + bn1 * 4);
        float* dA = &As[0][0];
        float* dB = &Bs[0][0];
        dA[ar0 * A_LD + ak0 * 4 + 0] = to_tf32(a0.x); dA[ar0 * A_LD + ak0 * 4 + 1] = to_tf32(a0.y);
        dA[ar0 * A_LD + ak0 * 4 + 2] = to_tf32(a0.z); dA[ar0 * A_LD + ak0 * 4 + 3] = to_tf32(a0.w);
        dA[ar1 * A_LD + ak1 * 4 + 0] = to_tf32(a1.x); dA[ar1 * A_LD + ak1 * 4 + 1] = to_tf32(a1.y);
        dA[ar1 * A_LD + ak1 * 4 + 2] = to_tf32(a1.z); dA[ar1 * A_LD + ak1 * 4 + 3] = to_tf32(a1.w);
        dB[br0 * B_LD + bn0 * 4 + 0] = to_tf32(b0.x); dB[br0 * B_LD + bn0 * 4 + 1] = to_tf32(b0.y);
        dB[br0 * B_LD + bn0 * 4 + 2] = to_tf32(b0.z); dB[br0 * B_LD + bn0 * 4 + 3] = to_tf32(b0.w);
        dB[br1 * B_LD + bn1 * 4 + 0] = to_tf32(b1.x); dB[br1 * B_LD + bn1 * 4 + 1] = to_tf32(b1.y);
        dB[br1 * B_LD + bn1 * 4 + 2] = to_tf32(b1.z); dB[br1 * B_LD + bn1 * 4 + 3] = to_tf32(b1.w);
    }
    __syncthreads();

    int buf = 0;
    for (int kt = 0; kt < K; kt += GBK) {
        const bool has_next = (kt + GBK) < K;
        float4 a0, a1, b0, b1;
        if (has_next) {
            const int kn = kt + GBK;
            a0 = *reinterpret_cast<const float4*>(A + (size_t)(row0 + ar0) * K + kn + ak0 * 4);
            a1 = *reinterpret_cast<const float4*>(A + (size_t)(row0 + ar1) * K + kn + ak1 * 4);
            b0 = *reinterpret_cast<const float4*>(W + (size_t)(kn + br0) * N + col0 + bn0 * 4);
            b1 = *reinterpret_cast<const float4*>(W + (size_t)(kn + br1) * N + col0 + bn1 * 4);
        }

        const float* sA = &As[buf][0];
        const float* sB = &Bs[buf][0];
#pragma unroll
        for (int ks = 0; ks < 2; ks++) {
            const int k0 = ks * 8;
            wmma::fragment<wmma::matrix_a, 16, 16, 8, wmma::precision::tf32, wmma::row_major> af[4];
            wmma::fragment<wmma::matrix_b, 16, 16, 8, wmma::precision::tf32, wmma::row_major> bf[2];
#pragma unroll
            for (int mf = 0; mf < 4; mf++)
                wmma::load_matrix_sync(af[mf], &sA[(wm * 64 + mf * 16) * A_LD + k0], A_LD);
#pragma unroll
            for (int nf = 0; nf < 2; nf++)
                wmma::load_matrix_sync(bf[nf], &sB[k0 * B_LD + wn * 32 + nf * 16], B_LD);
#pragma unroll
            for (int mf = 0; mf < 4; mf++)
#pragma unroll
                for (int nf = 0; nf < 2; nf++)
                    wmma::mma_sync(acc[mf][nf], af[mf], bf[nf], acc[mf][nf]);
        }

        if (has_next) {
            float* dA = &As[buf ^ 1][0];
            float* dB = &Bs[buf ^ 1][0];
            dA[ar0 * A_LD + ak0 * 4 + 0] = to_tf32(a0.x); dA[ar0 * A_LD + ak0 * 4 + 1] = to_tf32(a0.y);
            dA[ar0 * A_LD + ak0 * 4 + 2] = to_tf32(a0.z); dA[ar0 * A_LD + ak0 * 4 + 3] = to_tf32(a0.w);
            dA[ar1 * A_LD + ak1 * 4 + 0] = to_tf32(a1.x); dA[ar1 * A_LD + ak1 * 4 + 1] = to_tf32(a1.y);
            dA[ar1 * A_LD + ak1 * 4 + 2] = to_tf32(a1.z); dA[ar1 * A_LD + ak1 * 4 + 3] = to_tf32(a1.w);
            dB[br0 * B_LD + bn0 * 4 + 0] = to_tf32(b0.x); dB[br0 * B_LD + bn0 * 4 + 1] = to_tf32(b0.y);
            dB[br0 * B_LD + bn0 * 4 + 2] = to_tf32(b0.z); dB[br0 * B_LD + bn0 * 4 + 3] = to_tf32(b0.w);
            dB[br1 * B_LD + bn1 * 4 + 0] = to_tf32(b1.x); dB[br1 * B_LD + bn1 * 4 + 1] = to_tf32(b1.y);
            dB[br1 * B_LD + bn1 * 4 + 2] = to_tf32(b1.z); dB[br1 * B_LD + bn1 * 4 + 3] = to_tf32(b1.w);
        }
        __syncthreads();
        buf ^= 1;
    }

#pragma unroll
    for (int mf = 0; mf < 4; mf++)
#pragma unroll
        for (int nf = 0; nf < 2; nf++)
            wmma::store_matrix_sync(
                C + (size_t)(row0 + wm * 64 + mf * 16) * N + col0 + wn * 32 + nf * 16,
                acc[mf][nf], N, wmma::mem_row_major);
}

// ---------------------------------------------------------------------------
// Masked attention: tf32 wmma, exp+mask applied in-register on the
// accumulator fragment (mma.sync ISA layout), bitmask words for the mask,
// per-wn l partials merged once at the end. 3 syncs per KV tile.
// ---------------------------------------------------------------------------
#define TS  64
#define PAD 68

__global__ __launch_bounds__(256)
void attn_tf32(float* __restrict__ Og)
{
    extern __shared__ float sm[];
    float* Qs = sm;                 // [64][68]
    float* Ks = sm + TS * PAD;
    float* Vs = sm + 2 * TS * PAD;
    float* Ps = sm + 3 * TS * PAD;
    float* Ls = sm + 4 * TS * PAD;  // [4][64] per-wn row-sum partials

    const int qt = blockIdx.x;
    const int h  = blockIdx.y;
    const int b  = blockIdx.z;
    const int s0 = qt * TS;
    const int tid  = threadIdx.x;
    const int w    = tid >> 5;
    const int wm   = w >> 2;   // 0..1
    const int wn   = w & 3;    // 0..3
    const int lane = tid & 31;
    const int tx   = tid & 15;
    const int ty   = tid >> 4;
    const int r0   = ty * 4;

    const float* Qbase = g_Q + ((size_t)b * SEQ + s0) * DIM + h * HD;
    const float* Kbase = g_K + (size_t)b * SEQ * DIM + h * HD;
    const float* Vbase = g_V + (size_t)b * SEQ * DIM + h * HD;

    // load Q tile, fold ATT_SCALE, pre-round to tf32
#pragma unroll
    for (int it = 0; it < 4; it++) {
        int lin = tid + it * 256;
        int row = lin >> 4, q4 = lin & 15;
        float4 v = *reinterpret_cast<const float4*>(Qbase + (size_t)row * DIM + q4 * 4);
        Qs[row * PAD + q4 * 4 + 0] = to_tf32(v.x * ATT_SCALE);
        Qs[row * PAD + q4 * 4 + 1] = to_tf32(v.y * ATT_SCALE);
        Qs[row * PAD + q4 * 4 + 2] = to_tf32(v.z * ATT_SCALE);
        Qs[row * PAD + q4 * 4 + 3] = to_tf32(v.w * ATT_SCALE);
    }

    wmma::fragment<wmma::accumulator, 16, 16, 8, float> ofrag[2];
#pragma unroll
    for (int f = 0; f < 2; f++) wmma::fill_fragment(ofrag[f], 0.f);

    float lsum[2][2] = {{0.f, 0.f}, {0.f, 0.f}};   // [frag][rowhalf]

    // mask word column index pieces for this warp
    const int wrow = s0 + wm * 32 + (lane >> 2);   // + f*16 (+8)
    const int sh   = (wn & 1) * 16;                // shift within word

    for (int kt = 0; kt < SEQ; kt += TS) {
        // ---- load K / V tiles (pre-rounded) ----
#pragma unroll
        for (int it = 0; it < 4; it++) {
            int lin = tid + it * 256;
            int row = lin >> 4, q4 = lin & 15;
            float4 kv = *reinterpret_cast<const float4*>(Kbase + (size_t)(kt + row) * DIM + q4 * 4);
            float4 vv = *reinterpret_cast<const float4*>(Vbase + (size_t)(kt + row) * DIM + q4 * 4);
            Ks[row * PAD + q4 * 4 + 0] = to_tf32(kv.x);
            Ks[row * PAD + q4 * 4 + 1] = to_tf32(kv.y);
            Ks[row * PAD + q4 * 4 + 2] = to_tf32(kv.z);
            Ks[row * PAD + q4 * 4 + 3] = to_tf32(kv.w);
            Vs[row * PAD + q4 * 4 + 0] = to_tf32(vv.x);
            Vs[row * PAD + q4 * 4 + 1] = to_tf32(vv.y);
            Vs[row * PAD + q4 * 4 + 2] = to_tf32(vv.z);
            Vs[row * PAD + q4 * 4 + 3] = to_tf32(vv.w);
        }
        __syncthreads();

        // ---- S = (Q*scale) @ K^T ----
        wmma::fragment<wmma::accumulator, 16, 16, 8, float> sfrag[2];
#pragma unroll
        for (int f = 0; f < 2; f++) wmma::fill_fragment(sfrag[f], 0.f);

#pragma unroll
        for (int d0 = 0; d0 < HD; d0 += 8) {
            wmma::fragment<wmma::matrix_a, 16, 16, 8, wmma::precision::tf32, wmma::row_major> aq[2];
            wmma::fragment<wmma::matrix_b, 16, 16, 8, wmma::precision::tf32, wmma::col_major> bk;
#pragma unroll
            for (int f = 0; f < 2; f++)
                wmma::load_matrix_sync(aq[f], &Qs[(wm * 32 + f * 16) * PAD + d0], PAD);
            wmma::load_matrix_sync(bk, &Ks[(wn * 16) * PAD + d0], PAD);
#pragma unroll
            for (int f = 0; f < 2; f++)
                wmma::mma_sync(sfrag[f], aq[f], bk, sfrag[f]);
        }

        // ---- in-register masked exp + partial row sums; store P ----
        const int colw = (kt + wn * 16) >> 5;
#pragma unroll
        for (int f = 0; f < 2; f++) {
            uint32_t w0 = g_MB[(wrow + f * 16) * MBW + colw];
            uint32_t w8 = g_MB[(wrow + f * 16 + 8) * MBW + colw];
            uint32_t b0 = (w0 >> sh) & 0xFFFFu;
            uint32_t b8 = (w8 >> sh) & 0xFFFFu;
            float rs0 = 0.f, rs8 = 0.f;
#pragma unroll
            for (int g = 0; g < 2; g++) {
                const int cb = g * 8 + 2 * (lane & 3);
                float p;
                p = ((b0 >> cb) & 1u) ? fast_exp(sfrag[f].x[g * 4 + 0]) : 0.f;
                sfrag[f].x[g * 4 + 0] = to_tf32(p); rs0 += p;
                p = ((b0 >> (cb + 1)) & 1u) ? fast_exp(sfrag[f].x[g * 4 + 1]) : 0.f;
                sfrag[f].x[g * 4 + 1] = to_tf32(p); rs0 += p;
                p = ((b8 >> cb) & 1u) ? fast_exp(sfrag[f].x[g * 4 + 2]) : 0.f;
                sfrag[f].x[g * 4 + 2] = to_tf32(p); rs8 += p;
                p = ((b8 >> (cb + 1)) & 1u) ? fast_exp(sfrag[f].x[g * 4 + 3]) : 0.f;
                sfrag[f].x[g * 4 + 3] = to_tf32(p); rs8 += p;
            }
            rs0 += __shfl_xor_sync(0xffffffffu, rs0, 1);
            rs0 += __shfl_xor_sync(0xffffffffu, rs0, 2);
            rs8 += __shfl_xor_sync(0xffffffffu, rs8, 1);
            rs8 += __shfl_xor_sync(0xffffffffu, rs8, 2);
            lsum[f][0] += rs0;
            lsum[f][1] += rs8;
            wmma::store_matrix_sync(&Ps[(wm * 32 + f * 16) * PAD + wn * 16],
                                    sfrag[f], PAD, wmma::mem_row_major);
        }
        __syncthreads();

        // ---- O += P @ V ----
#pragma unroll
        for (int t0 = 0; t0 < TS; t0 += 8) {
            wmma::fragment<wmma::matrix_a, 16, 16, 8, wmma::precision::tf32, wmma::row_major> ap[2];
            wmma::fragment<wmma::matrix_b, 16, 16, 8, wmma::precision::tf32, wmma::row_major> bv;
#pragma unroll
            for (int f = 0; f < 2; f++)
                wmma::load_matrix_sync(ap[f], &Ps[(wm * 32 + f * 16) * PAD + t0], PAD);
            wmma::load_matrix_sync(bv, &Vs[t0 * PAD + wn * 16], PAD);
#pragma unroll
            for (int f = 0; f < 2; f++)
                wmma::mma_sync(ofrag[f], ap[f], bv, ofrag[f]);
        }
        __syncthreads();
    }

    // ---- publish l partials, O to smem ----
    if ((lane & 3) == 0) {
#pragma unroll
        for (int f = 0; f < 2; f++) {
            Ls[wn * 64 + wm * 32 + f * 16 + (lane >> 2)]     = lsum[f][0];
            Ls[wn * 64 + wm * 32 + f * 16 + (lane >> 2) + 8] = lsum[f][1];
        }
    }
#pragma unroll
    for (int f = 0; f < 2; f++)
        wmma::store_matrix_sync(&Ps[(wm * 32 + f * 16) * PAD + wn * 16],
                                ofrag[f], PAD, wmma::mem_row_major);
    __syncthreads();

    // ---- normalize + write context ----
#pragma unroll
    for (int i = 0; i < 4; i++) {
        int row = r0 + i;
        float l = Ls[row] + Ls[64 + row] + Ls[128 + row] + Ls[192 + row];
        float inv = 1.f / l;
        float* orow = Og + ((size_t)b * SEQ + s0 + row) * DIM + h * HD;
#pragma unroll
        for (int ww = 0; ww < 4; ww++) {
            int c = tx + 16 * ww;
            orow[c] = Ps[row * PAD + c] * inv;
        }
    }
}

// ---------------------------------------------------------------------------
// Launch
// ---------------------------------------------------------------------------
extern "C" void kernel_launch(void* const* d_in, const int* in_sizes, int n_in,
                              void* d_out, int out_size)
{
    const float* query = (const float*)d_in[0];
    const float* key   = (const float*)d_in[1];
    const float* value = (const float*)d_in[2];
    const int*   mask  = (const int*)  d_in[3];
    const float* Wq = (const float*)d_in[4];
    const float* bq = (const float*)d_in[5];
    const float* Wk = (const float*)d_in[6];
    const float* bk = (const float*)d_in[7];
    const float* Wv = (const float*)d_in[8];
    const float* bv = (const float*)d_in[9];
    const float* Wo = (const float*)d_in[10];
    const float* bo = (const float*)d_in[11];
    float* out = (float*)d_out;

    float *pQ, *pK, *pV, *pC;
    cudaGetSymbolAddress((void**)&pQ, g_Q);
    cudaGetSymbolAddress((void**)&pK, g_K);
    cudaGetSymbolAddress((void**)&pV, g_V);
    cudaGetSymbolAddress((void**)&pC, g_Ctx);

    const int M = BATCH * SEQ;   // 4096
    const int N = DIM;
    const int K = DIM;

    // mask -> bit words (overlaps QKV GEMM wave tail ordering-wise; cheap)
    mask_bits_kernel<<<SEQ * SEQ / 256, 256>>>(mask);

    // Fused Q/K/V projections
    dim3 qkv_grid(N / GBN, M / GBM, 3);
    gemm_tf32_bias<<<qkv_grid, 256>>>(query, Wq, bq, pQ,
                                      key,   Wk, bk, pK,
                                      value, Wv, bv, pV, M, N, K);

    // Attention
    const int attn_smem = (4 * TS * PAD + 4 * 64) * (int)sizeof(float);  // 70656 B
    cudaFuncSetAttribute(attn_tf32, cudaFuncAttributeMaxDynamicSharedMemorySize, attn_smem);
    attn_tf32<<<dim3(SEQ / TS, NH, BATCH), 256, attn_smem>>>(pC);

    // Output projection
    dim3 ggrid(N / GBN, M / GBM, 1);
    gemm_tf32_bias<<<ggrid, 256>>>(pC, Wo, bo, out,
                                   pC, Wo, bo, out,
                                   pC, Wo, bo, out, M, N, K);
}

// round 5
// speedup vs baseline: 2.7390x; 2.3861x over previous
#include <cuda_runtime.h>
#include <cuda_fp16.h>
#include <mma.h>
#include <cstdint>
#include <cstddef>

using namespace nvcuda;

// Problem constants
#define BATCH 2
#define SEQ   2048
#define DIM   1024
#define NH    16
#define HD    64
#define ATT_SCALE 0.125f
#define MBW   (SEQ / 32)

// Scratch
__device__ float g_Q[BATCH * SEQ * DIM];
__device__ float g_K[BATCH * SEQ * DIM];
__device__ float g_V[BATCH * SEQ * DIM];
__device__ float g_Ctx[BATCH * SEQ * DIM];
__device__ uint32_t g_MB[SEQ * MBW];

// fast exp on the FMA pipe
__device__ __forceinline__ float fast_exp(float x) {
    float n = rintf(x * 1.4426950408889634f);
    float r = fmaf(n, -0.6931471805599453f, x);
    float e = fmaf(r, 8.3333337e-3f, 4.1666668e-2f);
    e = fmaf(r, e, 0.16666667f);
    e = fmaf(r, e, 0.5f);
    e = fmaf(r, e, 1.0f);
    e = fmaf(r, e, 1.0f);
    int ni = (int)n;
    return e * __int_as_float((ni + 127) << 23);
}

// ---------------------------------------------------------------------------
// mask (int32) -> bitmask words
// ---------------------------------------------------------------------------
__global__ __launch_bounds__(256)
void mask_bits_kernel(const int* __restrict__ mask)
{
    int idx = blockIdx.x * 256 + threadIdx.x;
    uint32_t bit = (mask[idx] != 0) ? 1u : 0u;
    uint32_t word = __ballot_sync(0xffffffffu, bit);
    if ((threadIdx.x & 31) == 0) g_MB[idx >> 5] = word;
}

// ---------------------------------------------------------------------------
// FP16 GEMM + bias: C = A @ W + bias. 128x64x32 tile, double-buffered smem,
// 8 warps (4m x 2n), warp 32x32 via wmma m16n16k16 (fp32 acc).
// Manual epilogue uses the mma.sync acc layout:
//   x[g*4+{0,1}] -> (row lane>>2,   cols g*8 + 2*(lane&3) + {0,1})
//   x[g*4+{2,3}] -> (row lane>>2+8, same cols)
// blockIdx.z selects among 3 fused problems.
// ---------------------------------------------------------------------------
#define GBM 128
#define GBN 64
#define GBK 32
#define A_LDH 40    // 32 + 8 halfs
#define B_LDH 72    // 64 + 8 halfs

__global__ __launch_bounds__(256, 2)
void gemm_fp16_bias(const float* __restrict__ A0, const float* __restrict__ W0,
                    const float* __restrict__ bias0, float* __restrict__ C0,
                    const float* __restrict__ A1, const float* __restrict__ W1,
                    const float* __restrict__ bias1, float* __restrict__ C1,
                    const float* __restrict__ A2, const float* __restrict__ W2,
                    const float* __restrict__ bias2, float* __restrict__ C2,
                    int M, int N, int K)
{
    __shared__ __half As[2][GBM * A_LDH];   // 2*5120*2 = 20480B
    __shared__ __half Bs[2][GBK * B_LDH];   // 2*2304*2 =  9216B

    const int z = blockIdx.z;
    const float* A    = (z == 0) ? A0    : (z == 1) ? A1    : A2;
    const float* W    = (z == 0) ? W0    : (z == 1) ? W1    : W2;
    const float* bias = (z == 0) ? bias0 : (z == 1) ? bias1 : bias2;
    float*       C    = (z == 0) ? C0    : (z == 1) ? C1    : C2;

    const int tid  = threadIdx.x;
    const int lane = tid & 31;
    const int w    = tid >> 5;
    const int wm   = w >> 1;    // 0..3 -> 32 rows
    const int wn   = w & 1;     // 0..1 -> 32 cols
    const int row0 = blockIdx.y * GBM;
    const int col0 = blockIdx.x * GBN;

    wmma::fragment<wmma::accumulator, 16, 16, 16, float> acc[2][2];
#pragma unroll
    for (int mf = 0; mf < 2; mf++)
#pragma unroll
        for (int nf = 0; nf < 2; nf++)
            wmma::fill_fragment(acc[mf][nf], 0.f);

    // per-thread load coords
    int ar[4], ak[4];
#pragma unroll
    for (int it = 0; it < 4; it++) { int q = tid + it * 256; ar[it] = q >> 3; ak[it] = q & 7; }
    int bk_[2], bn_[2];
#pragma unroll
    for (int it = 0; it < 2; it++) { int q = tid + it * 256; bk_[it] = q >> 4; bn_[it] = q & 15; }

    // prolog: stage kt=0 into buffer 0
#pragma unroll
    for (int it = 0; it < 4; it++) {
        float4 v = *reinterpret_cast<const float4*>(A + (size_t)(row0 + ar[it]) * K + ak[it] * 4);
        __half2* dst = reinterpret_cast<__half2*>(&As[0][ar[it] * A_LDH + ak[it] * 4]);
        dst[0] = __floats2half2_rn(v.x, v.y);
        dst[1] = __floats2half2_rn(v.z, v.w);
    }
#pragma unroll
    for (int it = 0; it < 2; it++) {
        float4 v = *reinterpret_cast<const float4*>(W + (size_t)bk_[it] * N + col0 + bn_[it] * 4);
        __half2* dst = reinterpret_cast<__half2*>(&Bs[0][bk_[it] * B_LDH + bn_[it] * 4]);
        dst[0] = __floats2half2_rn(v.x, v.y);
        dst[1] = __floats2half2_rn(v.z, v.w);
    }
    __syncthreads();

    int buf = 0;
    for (int kt = 0; kt < K; kt += GBK) {
        const bool has_next = (kt + GBK) < K;
        float4 pa[4], pb[2];
        if (has_next) {
            const int kn = kt + GBK;
#pragma unroll
            for (int it = 0; it < 4; it++)
                pa[it] = *reinterpret_cast<const float4*>(A + (size_t)(row0 + ar[it]) * K + kn + ak[it] * 4);
#pragma unroll
            for (int it = 0; it < 2; it++)
                pb[it] = *reinterpret_cast<const float4*>(W + (size_t)(kn + bk_[it]) * N + col0 + bn_[it] * 4);
        }

        const __half* sA = &As[buf][0];
        const __half* sB = &Bs[buf][0];
#pragma unroll
        for (int ks = 0; ks < 2; ks++) {
            const int k0 = ks * 16;
            wmma::fragment<wmma::matrix_a, 16, 16, 16, __half, wmma::row_major> af[2];
            wmma::fragment<wmma::matrix_b, 16, 16, 16, __half, wmma::row_major> bf[2];
#pragma unroll
            for (int mf = 0; mf < 2; mf++)
                wmma::load_matrix_sync(af[mf], &sA[(wm * 32 + mf * 16) * A_LDH + k0], A_LDH);
#pragma unroll
            for (int nf = 0; nf < 2; nf++)
                wmma::load_matrix_sync(bf[nf], &sB[k0 * B_LDH + wn * 32 + nf * 16], B_LDH);
#pragma unroll
            for (int mf = 0; mf < 2; mf++)
#pragma unroll
                for (int nf = 0; nf < 2; nf++)
                    wmma::mma_sync(acc[mf][nf], af[mf], bf[nf], acc[mf][nf]);
        }

        if (has_next) {
            __half* dA = &As[buf ^ 1][0];
            __half* dB = &Bs[buf ^ 1][0];
#pragma unroll
            for (int it = 0; it < 4; it++) {
                __half2* dst = reinterpret_cast<__half2*>(&dA[ar[it] * A_LDH + ak[it] * 4]);
                dst[0] = __floats2half2_rn(pa[it].x, pa[it].y);
                dst[1] = __floats2half2_rn(pa[it].z, pa[it].w);
            }
#pragma unroll
            for (int it = 0; it < 2; it++) {
                __half2* dst = reinterpret_cast<__half2*>(&dB[bk_[it] * B_LDH + bn_[it] * 4]);
                dst[0] = __floats2half2_rn(pb[it].x, pb[it].y);
                dst[1] = __floats2half2_rn(pb[it].z, pb[it].w);
            }
        }
        __syncthreads();
        buf ^= 1;
    }

    // ---- epilogue: manual store with bias (acc layout as documented above) ----
    float2 bb[2][2];
#pragma unroll
    for (int nf = 0; nf < 2; nf++)
#pragma unroll
        for (int g = 0; g < 2; g++)
            bb[nf][g] = *reinterpret_cast<const float2*>(
                &bias[col0 + wn * 32 + nf * 16 + g * 8 + 2 * (lane & 3)]);

#pragma unroll
    for (int mf = 0; mf < 2; mf++) {
        const int r  = row0 + wm * 32 + mf * 16 + (lane >> 2);
#pragma unroll
        for (int nf = 0; nf < 2; nf++) {
#pragma unroll
            for (int g = 0; g < 2; g++) {
                const int col = col0 + wn * 32 + nf * 16 + g * 8 + 2 * (lane & 3);
                float2 lo, hi;
                lo.x = acc[mf][nf].x[g * 4 + 0] + bb[nf][g].x;
                lo.y = acc[mf][nf].x[g * 4 + 1] + bb[nf][g].y;
                hi.x = acc[mf][nf].x[g * 4 + 2] + bb[nf][g].x;
                hi.y = acc[mf][nf].x[g * 4 + 3] + bb[nf][g].y;
                *reinterpret_cast<float2*>(&C[(size_t)r * N + col])       = lo;
                *reinterpret_cast<float2*>(&C[(size_t)(r + 8) * N + col]) = hi;
            }
        }
    }
}

// ---------------------------------------------------------------------------
// Masked attention, fp16 wmma, Q-tile 128 x KV-tile 64, no max subtraction.
// exp+mask in-register on acc fragments; O written directly from fragments.
// Block: 256 threads = 8 warps (2m x 4n): wm -> 64 rows, wn -> 16 cols.
// ---------------------------------------------------------------------------
#define TSM 128
#define TSN 64
#define PADP 72

__global__ __launch_bounds__(256, 2)
void attn_fp16(float* __restrict__ Og)
{
    extern __shared__ char smraw[];
    __half* Qs = reinterpret_cast<__half*>(smraw);        // [128][72]
    __half* Ks = Qs + TSM * PADP;                         // [64][72]
    __half* Vs = Ks + TSN * PADP;                         // [64][72]
    __half* Ps = Vs + TSN * PADP;                         // [128][72]
    float*  Ls = reinterpret_cast<float*>(Ps + TSM * PADP);  // [4][128]

    const int qt = blockIdx.x;
    const int h  = blockIdx.y;
    const int b  = blockIdx.z;
    const int s0 = qt * TSM;
    const int tid  = threadIdx.x;
    const int lane = tid & 31;
    const int w    = tid >> 5;
    const int wm   = w >> 2;   // 0..1 : 64 rows
    const int wn   = w & 3;    // 0..3 : 16 cols

    const float* Qbase = g_Q + ((size_t)b * SEQ + s0) * DIM + h * HD;
    const float* Kbase = g_K + (size_t)b * SEQ * DIM + h * HD;
    const float* Vbase = g_V + (size_t)b * SEQ * DIM + h * HD;

    // load Q tile (fold ATT_SCALE): 128x64 = 2048 float4, 8/thread
#pragma unroll
    for (int it = 0; it < 8; it++) {
        int lin = tid + it * 256;
        int row = lin >> 4, q4 = lin & 15;
        float4 v = *reinterpret_cast<const float4*>(Qbase + (size_t)row * DIM + q4 * 4);
        __half2* dst = reinterpret_cast<__half2*>(&Qs[row * PADP + q4 * 4]);
        dst[0] = __floats2half2_rn(v.x * ATT_SCALE, v.y * ATT_SCALE);
        dst[1] = __floats2half2_rn(v.z * ATT_SCALE, v.w * ATT_SCALE);
    }

    wmma::fragment<wmma::accumulator, 16, 16, 16, float> ofrag[4];
#pragma unroll
    for (int f = 0; f < 4; f++) wmma::fill_fragment(ofrag[f], 0.f);

    float lsum[4][2];
#pragma unroll
    for (int f = 0; f < 4; f++) { lsum[f][0] = 0.f; lsum[f][1] = 0.f; }

    const int wrow = s0 + wm * 64 + (lane >> 2);
    const int sh   = (wn & 1) * 16;

    for (int kt = 0; kt < SEQ; kt += TSN) {
        // ---- load K / V tiles: 64x64 each, 4 float4/thread each ----
#pragma unroll
        for (int it = 0; it < 4; it++) {
            int lin = tid + it * 256;
            int row = lin >> 4, q4 = lin & 15;
            float4 kv = *reinterpret_cast<const float4*>(Kbase + (size_t)(kt + row) * DIM + q4 * 4);
            float4 vv = *reinterpret_cast<const float4*>(Vbase + (size_t)(kt + row) * DIM + q4 * 4);
            __half2* dk = reinterpret_cast<__half2*>(&Ks[row * PADP + q4 * 4]);
            dk[0] = __floats2half2_rn(kv.x, kv.y);
            dk[1] = __floats2half2_rn(kv.z, kv.w);
            __half2* dv = reinterpret_cast<__half2*>(&Vs[row * PADP + q4 * 4]);
            dv[0] = __floats2half2_rn(vv.x, vv.y);
            dv[1] = __floats2half2_rn(vv.z, vv.w);
        }
        __syncthreads();

        // prefetch mask words (latency hidden under S mma)
        const int colw = (kt + wn * 16) >> 5;
        uint32_t mw0[4], mw8[4];
#pragma unroll
        for (int f = 0; f < 4; f++) {
            mw0[f] = g_MB[(wrow + f * 16) * MBW + colw];
            mw8[f] = g_MB[(wrow + f * 16 + 8) * MBW + colw];
        }

        // ---- S = (Q*scale) @ K^T ----
        wmma::fragment<wmma::accumulator, 16, 16, 16, float> sfrag[4];
#pragma unroll
        for (int f = 0; f < 4; f++) wmma::fill_fragment(sfrag[f], 0.f);

#pragma unroll
        for (int d0 = 0; d0 < HD; d0 += 16) {
            wmma::fragment<wmma::matrix_b, 16, 16, 16, __half, wmma::col_major> bkf;
            wmma::load_matrix_sync(bkf, &Ks[(wn * 16) * PADP + d0], PADP);
#pragma unroll
            for (int f = 0; f < 4; f++) {
                wmma::fragment<wmma::matrix_a, 16, 16, 16, __half, wmma::row_major> aq;
                wmma::load_matrix_sync(aq, &Qs[(wm * 64 + f * 16) * PADP + d0], PADP);
                wmma::mma_sync(sfrag[f], aq, bkf, sfrag[f]);
            }
        }

        // ---- in-register masked exp + partial row sums; store P (half) ----
#pragma unroll
        for (int f = 0; f < 4; f++) {
            uint32_t b0 = (mw0[f] >> sh) & 0xFFFFu;
            uint32_t b8 = (mw8[f] >> sh) & 0xFFFFu;
            float rs0 = 0.f, rs8 = 0.f;
            const int prow = wm * 64 + f * 16 + (lane >> 2);
#pragma unroll
            for (int g = 0; g < 2; g++) {
                const int cb = g * 8 + 2 * (lane & 3);
                float p0 = ((b0 >> cb)       & 1u) ? fast_exp(sfrag[f].x[g * 4 + 0]) : 0.f;
                float p1 = ((b0 >> (cb + 1)) & 1u) ? fast_exp(sfrag[f].x[g * 4 + 1]) : 0.f;
                float p2 = ((b8 >> cb)       & 1u) ? fast_exp(sfrag[f].x[g * 4 + 2]) : 0.f;
                float p3 = ((b8 >> (cb + 1)) & 1u) ? fast_exp(sfrag[f].x[g * 4 + 3]) : 0.f;
                rs0 += p0 + p1;
                rs8 += p2 + p3;
                const int col = wn * 16 + cb;
                *reinterpret_cast<__half2*>(&Ps[prow * PADP + col])       = __floats2half2_rn(p0, p1);
                *reinterpret_cast<__half2*>(&Ps[(prow + 8) * PADP + col]) = __floats2half2_rn(p2, p3);
            }
            rs0 += __shfl_xor_sync(0xffffffffu, rs0, 1);
            rs0 += __shfl_xor_sync(0xffffffffu, rs0, 2);
            rs8 += __shfl_xor_sync(0xffffffffu, rs8, 1);
            rs8 += __shfl_xor_sync(0xffffffffu, rs8, 2);
            lsum[f][0] += rs0;
            lsum[f][1] += rs8;
        }
        __syncthreads();

        // ---- O += P @ V ----
#pragma unroll
        for (int t0 = 0; t0 < TSN; t0 += 16) {
            wmma::fragment<wmma::matrix_b, 16, 16, 16, __half, wmma::row_major> bvf;
            wmma::load_matrix_sync(bvf, &Vs[t0 * PADP + wn * 16], PADP);
#pragma unroll
            for (int f = 0; f < 4; f++) {
                wmma::fragment<wmma::matrix_a, 16, 16, 16, __half, wmma::row_major> ap;
                wmma::load_matrix_sync(ap, &Ps[(wm * 64 + f * 16) * PADP + t0], PADP);
                wmma::mma_sync(ofrag[f], ap, bvf, ofrag[f]);
            }
        }
        __syncthreads();
    }

    // ---- publish l partials ----
    if ((lane & 3) == 0) {
#pragma unroll
        for (int f = 0; f < 4; f++) {
            Ls[wn * TSM + wm * 64 + f * 16 + (lane >> 2)]     = lsum[f][0];
            Ls[wn * TSM + wm * 64 + f * 16 + (lane >> 2) + 8] = lsum[f][1];
        }
    }
    __syncthreads();

    // ---- normalize in-register, write O directly from fragments ----
#pragma unroll
    for (int f = 0; f < 4; f++) {
        const int row  = wm * 64 + f * 16 + (lane >> 2);
        const float l0 = Ls[row] + Ls[TSM + row] + Ls[2 * TSM + row] + Ls[3 * TSM + row];
        const float l8 = Ls[row + 8] + Ls[TSM + row + 8] + Ls[2 * TSM + row + 8] + Ls[3 * TSM + row + 8];
        const float inv0 = 1.f / l0;
        const float inv8 = 1.f / l8;
        float* o0 = Og + ((size_t)b * SEQ + s0 + row) * DIM + h * HD;
        float* o8 = Og + ((size_t)b * SEQ + s0 + row + 8) * DIM + h * HD;
#pragma unroll
        for (int g = 0; g < 2; g++) {
            const int col = wn * 16 + g * 8 + 2 * (lane & 3);
            float2 lo, hi;
            lo.x = ofrag[f].x[g * 4 + 0] * inv0;
            lo.y = ofrag[f].x[g * 4 + 1] * inv0;
            hi.x = ofrag[f].x[g * 4 + 2] * inv8;
            hi.y = ofrag[f].x[g * 4 + 3] * inv8;
            *reinterpret_cast<float2*>(&o0[col]) = lo;
            *reinterpret_cast<float2*>(&o8[col]) = hi;
        }
    }
}

// ---------------------------------------------------------------------------
// Launch
// ---------------------------------------------------------------------------
extern "C" void kernel_launch(void* const* d_in, const int* in_sizes, int n_in,
                              void* d_out, int out_size)
{
    const float* query = (const float*)d_in[0];
    const float* key   = (const float*)d_in[1];
    const float* value = (const float*)d_in[2];
    const int*   mask  = (const int*)  d_in[3];
    const float* Wq = (const float*)d_in[4];
    const float* bq = (const float*)d_in[5];
    const float* Wk = (const float*)d_in[6];
    const float* bk = (const float*)d_in[7];
    const float* Wv = (const float*)d_in[8];
    const float* bv = (const float*)d_in[9];
    const float* Wo = (const float*)d_in[10];
    const float* bo = (const float*)d_in[11];
    float* out = (float*)d_out;

    float *pQ, *pK, *pV, *pC;
    cudaGetSymbolAddress((void**)&pQ, g_Q);
    cudaGetSymbolAddress((void**)&pK, g_K);
    cudaGetSymbolAddress((void**)&pV, g_V);
    cudaGetSymbolAddress((void**)&pC, g_Ctx);

    const int M = BATCH * SEQ;   // 4096
    const int N = DIM;
    const int K = DIM;

    mask_bits_kernel<<<SEQ * SEQ / 256, 256>>>(mask);

    dim3 qkv_grid(N / GBN, M / GBM, 3);   // (16, 32, 3)
    gemm_fp16_bias<<<qkv_grid, 256>>>(query, Wq, bq, pQ,
                                      key,   Wk, bk, pK,
                                      value, Wv, bv, pV, M, N, K);

    const int attn_smem = (2 * TSM * PADP + 2 * TSN * PADP) * 2 + 4 * TSM * 4;  // 57344 B
    cudaFuncSetAttribute(attn_fp16, cudaFuncAttributeMaxDynamicSharedMemorySize, attn_smem);
    attn_fp16<<<dim3(SEQ / TSM, NH, BATCH), 256, attn_smem>>>(pC);

    dim3 ogrid(N / GBN, M / GBM, 1);
    gemm_fp16_bias<<<ogrid, 256>>>(pC, Wo, bo, out,
                                   pC, Wo, bo, out,
                                   pC, Wo, bo, out, M, N, K);
}